// round 11
// baseline (speedup 1.0000x reference)
#include <cuda_runtime.h>
#include <cstdint>

// out[b, q, dv] = (1/SK) * sum_k value[b, k, dv]
// (q and k are the same broadcast scalar -> all logits equal -> softmax uniform
//  -> output = mean of value over SK, independent of query and q_param.)
//
// Fused single kernel, pipelined per batch: 32 CTAs/batch each reduce 64 rows;
// last arriver combines partials into one final 512B row + release flag;
// peers spin on the flag and stream their 64 output rows. Early batches write
// while late batches still read, hiding the read under the L2 write-cap floor.

#define B   16
#define SQ  2048
#define SK  2048
#define DV  128
#define SPB 32                    // CTAs (splits) per batch
#define RPB (SK / SPB)            // 64 rows per CTA

__device__ float4 g_part[B * SPB * 32];  // per-(b,split) partial rows
__device__ float4 g_final[B * 32];       // per-batch final scaled row
__device__ int    g_cnt[B];              // arrivals   (zero-init, self-reset)
__device__ int    g_flag[B];             // final-ready(zero-init, self-reset)
__device__ int    g_done[B];             // finishers  (zero-init, self-reset)

__global__ void __launch_bounds__(256, 4)
fused_kernel(const float4* __restrict__ value, float4* __restrict__ out) {
    const int b   = blockIdx.y;
    const int sp  = blockIdx.x;           // 0..31
    const int tid = threadIdx.x;
    const int dv4 = tid & 31;             // float4 column
    const int rg  = tid >> 5;             // 0..7

    __shared__ float4 tmp[256];
    __shared__ float4 fin[32];
    __shared__ int s_last;

    // ---- Phase A: reduce rows [sp*64, sp*64+64) ----
    const float4* base = value + ((size_t)b * SK + sp * RPB + rg) * (DV / 4) + dv4;
    float4 s = make_float4(0.f, 0.f, 0.f, 0.f);
    #pragma unroll
    for (int k = 0; k < RPB / 8; ++k) {
        float4 v = base[(size_t)k * 8 * (DV / 4)];
        s.x += v.x; s.y += v.y; s.z += v.z; s.w += v.w;
    }
    tmp[tid] = s;
    __syncthreads();

    if (tid < 32) {
        float4 a = tmp[tid];
        #pragma unroll
        for (int g = 1; g < 8; ++g) {
            float4 v = tmp[g * 32 + tid];
            a.x += v.x; a.y += v.y; a.z += v.z; a.w += v.w;
        }
        g_part[(b * SPB + sp) * 32 + tid] = a;
    }
    __syncthreads();

    // ---- Arrive; last arriver becomes the combiner ----
    if (tid == 0) {
        __threadfence();                          // publish g_part
        s_last = (atomicAdd(&g_cnt[b], 1) == SPB - 1);
    }
    __syncthreads();

    if (s_last) {
        // combine 32 partials -> final scaled row (256 thr, 4 loads each)
        const int spg = tid >> 5;                 // 0..7
        float4 a = make_float4(0.f, 0.f, 0.f, 0.f);
        #pragma unroll
        for (int i = 0; i < 4; ++i) {
            float4 v = g_part[(b * SPB + (spg + i * 8)) * 32 + dv4];
            a.x += v.x; a.y += v.y; a.z += v.z; a.w += v.w;
        }
        tmp[tid] = a;
        __syncthreads();
        if (tid < 32) {
            const float inv = 1.0f / (float)SK;
            float4 a2 = tmp[tid];
            #pragma unroll
            for (int g = 1; g < 8; ++g) {
                float4 v = tmp[g * 32 + tid];
                a2.x += v.x; a2.y += v.y; a2.z += v.z; a2.w += v.w;
            }
            a2.x *= inv; a2.y *= inv; a2.z *= inv; a2.w *= inv;
            g_final[b * 32 + tid] = a2;
        }
        __syncthreads();
        if (tid == 0) {
            asm volatile("st.release.gpu.global.s32 [%0], %1;"
                         :: "l"(&g_flag[b]), "r"(1) : "memory");
        }
    } else if (tid == 0) {
        int f;
        do {
            asm volatile("ld.acquire.gpu.global.s32 %0, [%1];"
                         : "=r"(f) : "l"(&g_flag[b]) : "memory");
            if (!f) __nanosleep(32);
        } while (!f);
    }
    __syncthreads();

    // ---- Load final row, stream 64 output rows ----
    if (tid < 32) fin[tid] = g_final[b * 32 + tid];
    __syncthreads();

    {
        const float4 v = fin[dv4];
        float4* o = out + ((size_t)b * SQ + sp * RPB + rg) * (DV / 4) + dv4;
        #pragma unroll
        for (int i = 0; i < 8; ++i) {
            o[(size_t)i * 8 * (DV / 4)] = v;
        }
    }

    // ---- Self-reset (last finisher per batch) ----
    if (tid == 0) {
        if (atomicAdd(&g_done[b], 1) == SPB - 1) {
            g_done[b] = 0;
            g_flag[b] = 0;
            g_cnt[b]  = 0;
        }
    }
}

extern "C" void kernel_launch(void* const* d_in, const int* in_sizes, int n_in,
                              void* d_out, int out_size) {
    // inputs: query[B,SQ,D], key[B,SK,D], value[B,SK,DV], q_param[1,1]
    const float4* value = (const float4*)d_in[2];
    float4* out = (float4*)d_out;

    dim3 grid(SPB, B);
    fused_kernel<<<grid, 256>>>(value, out);
}

// round 12
// speedup vs baseline: 1.1905x; 1.1905x over previous
#include <cuda_runtime.h>

// out[b, q, dv] = (1/SK) * sum_k value[b, k, dv]
// (q and k are the same broadcast scalar -> all logits equal -> softmax uniform
//  -> output = mean of value over SK, independent of query and q_param.)
//
// Evidence-locked structure: serial read phase then write phase (overlap
// measurably degrades combined L2 throughput on this chip). Read phase
// maximizes MLP; write phase is at the ~2.25 TB/s store-path cap.

#define B   16
#define SQ  2048
#define SK  2048
#define DV  128
#define SPB 8                    // splits (CTAs) per batch in reduce
#define RPC (SK / SPB)           // 256 rows per reduce CTA

__device__ float4 g_part[B * SPB * 32];   // per-(b,split) partial row (512B)

// grid (B, SPB) = 128 CTAs, block 512. Each CTA reduces 256 rows.
// Each thread: 16 independent float4 loads, fully unrolled (MLP=16).
__global__ void __launch_bounds__(512)
reduce_kernel(const float4* __restrict__ value) {
    const int b   = blockIdx.x;
    const int sp  = blockIdx.y;
    const int tid = threadIdx.x;
    const int dv4 = tid & 31;            // float4 column
    const int rg  = tid >> 5;            // 0..15

    const float4* base = value + ((size_t)b * SK + sp * RPC + rg) * (DV / 4) + dv4;

    float4 v[16];
    #pragma unroll
    for (int k = 0; k < 16; ++k) {
        v[k] = base[(size_t)k * 16 * (DV / 4)];
    }
    float4 s = v[0];
    #pragma unroll
    for (int k = 1; k < 16; ++k) {
        s.x += v[k].x; s.y += v[k].y; s.z += v[k].z; s.w += v[k].w;
    }

    __shared__ float4 tmp[512];
    tmp[tid] = s;
    __syncthreads();

    if (tid < 32) {
        float4 a = tmp[tid];
        #pragma unroll
        for (int g = 1; g < 16; ++g) {
            float4 w = tmp[g * 32 + tid];
            a.x += w.x; a.y += w.y; a.z += w.z; a.w += w.w;
        }
        g_part[(b * SPB + sp) * 32 + tid] = a;
    }
}

// grid (64, B) = 1024 CTAs, block 256. Each CTA writes 32 rows of batch b.
// Streaming stores (evict-first) for the 16 MiB output.
__global__ void __launch_bounds__(256)
broadcast_kernel(float4* __restrict__ out) {
    const int b     = blockIdx.y;
    const int chunk = blockIdx.x;         // 32-row chunk
    const int tid   = threadIdx.x;
    const int dv4   = tid & 31;
    const int rg    = tid >> 5;           // 0..7

    __shared__ float4 tmp[256];
    __shared__ float4 fin[32];

    float4* o = out + ((size_t)b * SQ + chunk * 32 + rg) * (DV / 4) + dv4;

    cudaGridDependencySynchronize();

    // combine: one global load per thread (8 splits x 32 columns)
    tmp[tid] = g_part[(b * SPB + rg) * 32 + dv4];
    __syncthreads();

    if (tid < 32) {
        const float inv = 1.0f / (float)SK;
        float4 a = tmp[tid];
        #pragma unroll
        for (int g = 1; g < 8; ++g) {
            float4 v = tmp[g * 32 + tid];
            a.x += v.x; a.y += v.y; a.z += v.z; a.w += v.w;
        }
        a.x *= inv; a.y *= inv; a.z *= inv; a.w *= inv;
        fin[tid] = a;
    }
    __syncthreads();

    const float4 v = fin[dv4];
    #pragma unroll
    for (int i = 0; i < 4; ++i) {
        float4* p = o + (size_t)i * 8 * (DV / 4);
        asm volatile("st.global.cs.v4.f32 [%0], {%1,%2,%3,%4};"
                     :: "l"(p), "f"(v.x), "f"(v.y), "f"(v.z), "f"(v.w)
                     : "memory");
    }
}

extern "C" void kernel_launch(void* const* d_in, const int* in_sizes, int n_in,
                              void* d_out, int out_size) {
    // inputs: query[B,SQ,D], key[B,SK,D], value[B,SK,DV], q_param[1,1]
    const float4* value = (const float4*)d_in[2];
    float4* out = (float4*)d_out;

    {
        dim3 rgrid(B, SPB);
        reduce_kernel<<<rgrid, 512>>>(value);
    }

    {
        cudaLaunchConfig_t cfg = {};
        cfg.gridDim  = dim3(64, B, 1);
        cfg.blockDim = dim3(256, 1, 1);
        cfg.dynamicSmemBytes = 0;
        cfg.stream = 0;

        cudaLaunchAttribute attr[1];
        attr[0].id = cudaLaunchAttributeProgrammaticStreamSerialization;
        attr[0].val.programmaticStreamSerializationAllowed = 1;
        cfg.attrs = attr;
        cfg.numAttrs = 1;

        cudaLaunchKernelEx(&cfg, broadcast_kernel, out);
    }
}